// round 15
// baseline (speedup 1.0000x reference)
#include <cuda_runtime.h>
#include <cuda_fp16.h>
#include <mma.h>
#include <stdint.h>

using namespace nvcuda;

#define KK 128
#define BATCH 256
#define DD 1024
#define BK (BATCH*KK)
#define LDA 136           // halves per A/W smem row (272 B)
#define LDS 132           // floats per S smem row

// static scratch (allocation-free rule)
__device__ __half g_sh0[256 * BATCH * KK];
__device__ __half g_sh1[64 * BATCH * KK];
__device__ float  g_m0[256 * BATCH];
__device__ float  g_m1[64 * BATCH];
__device__ __half g_wh[1023 * KK * KK];      // softmax(W) fp16

// ---- pair32 smem layout ----
#define SM_W0   0
#define SM_W1   34816
#define SM_A    69632
#define SM_S0   78336
#define SM_MSUM 95232
#define SMEM_BYTES (SM_MSUM + 192)

// ---- pair64 (non-leaf) smem layout ----
#define P64_W0   0
#define P64_W1   34816
#define P64_AR   34816      // alias of W1
#define P64_A0   69632
#define P64_A1   87040
#define P64_S0   69632      // alias A0+A1
#define P64_MSUM 104448
#define P64_BYTES (P64_MSUM + 256)

// ---- persistent leaf smem layout ----
#define LP_W0   0           // cycles Wc0 / Wup / Wc0-reload
#define LP_W1   34816       // Wc1 persistent
#define LP_A0   69632
#define LP_A1   87040
#define LP_S0   69632       // alias A0+A1
#define LP_AR   87040       // alias A1 (written after all S0 reads done)
#define LP_MSUM 104448      // 64 f32
#define LP_PM   104704      // 10x128 f32
#define LP_BYTES (LP_PM + 5120 + 64)   // ~107.3 KB -> 2 blocks/SM

// ---------------- helpers ----------------
static __device__ __forceinline__ uint32_t smem_u32(const void* p) {
    uint32_t a;
    asm("{ .reg .u64 t; cvta.to.shared.u64 t, %1; cvt.u32.u64 %0, t; }" : "=r"(a) : "l"(p));
    return a;
}
static __device__ __forceinline__ void cp_async16(uint32_t dst, const void* src) {
    asm volatile("cp.async.cg.shared.global [%0], [%1], 16;" :: "r"(dst), "l"(src));
}
static __device__ __forceinline__ void cp_commit() {
    asm volatile("cp.async.commit_group;" ::: "memory");
}
template<int N> static __device__ __forceinline__ void cp_wait() {
    asm volatile("cp.async.wait_group %0;" :: "n"(N) : "memory");
}
static __device__ __forceinline__ float warp_max(float m) {
    #pragma unroll
    for (int o = 16; o; o >>= 1) m = fmaxf(m, __shfl_xor_sync(0xffffffffu, m, o));
    return m;
}
static __device__ __forceinline__ float max4(float4 v) {
    return fmaxf(fmaxf(v.x, v.y), fmaxf(v.z, v.w));
}

// ---------------- K0: softmax(W) -> fp16 ----------------
__global__ void __launch_bounds__(256) softmax_w_kernel(const float* __restrict__ w) {
    const int node = blockIdx.x;
    const int wid = threadIdx.x >> 5, lane = threadIdx.x & 31;
    const float* wn = w + (size_t)node * (KK * KK);
    __half* out = g_wh + (size_t)node * (KK * KK);
    for (int i = wid; i < KK; i += 8) {
        float4 v = ((const float4*)(wn + i * KK))[lane];
        float m = warp_max(max4(v));
        float e0 = __expf(v.x - m), e1 = __expf(v.y - m);
        float e2 = __expf(v.z - m), e3 = __expf(v.w - m);
        float s = e0 + e1 + e2 + e3;
        #pragma unroll
        for (int o = 16; o; o >>= 1) s += __shfl_xor_sync(0xffffffffu, s, o);
        float inv = 1.0f / s;
        __half2 h0 = __floats2half2_rn(e0 * inv, e1 * inv);
        __half2 h1 = __floats2half2_rn(e2 * inv, e3 * inv);
        uint2 pk; pk.x = *(uint32_t*)&h0; pk.y = *(uint32_t*)&h1;
        *(uint2*)&out[i * KK + 4 * lane] = pk;
    }
}

using AccFrag = wmma::fragment<wmma::accumulator, 16, 16, 16, float>;

// 32x128x128: warp tile 16m x 32n
static __device__ __forceinline__ void gemm32_acc(const __half* As, const __half* Wh,
                                                  AccFrag acc[2], int wid) {
    const int m_base = (wid & 1) * 16, n_base = (wid >> 1) * 32;
    wmma::fill_fragment(acc[0], 0.0f);
    wmma::fill_fragment(acc[1], 0.0f);
    #pragma unroll
    for (int k = 0; k < 8; k++) {
        wmma::fragment<wmma::matrix_a, 16, 16, 16, __half, wmma::row_major> af;
        wmma::load_matrix_sync(af, &As[m_base * LDA + 16 * k], LDA);
        #pragma unroll
        for (int j = 0; j < 2; j++) {
            wmma::fragment<wmma::matrix_b, 16, 16, 16, __half, wmma::col_major> bf;
            wmma::load_matrix_sync(bf, &Wh[(n_base + 16 * j) * LDA + 16 * k], LDA);
            wmma::mma_sync(acc[j], af, bf, acc[j]);
        }
    }
}
static __device__ __forceinline__ void store_acc32(AccFrag acc[2], float* Out, int wid) {
    const int m_base = (wid & 1) * 16, n_base = (wid >> 1) * 32;
    #pragma unroll
    for (int j = 0; j < 2; j++)
        wmma::store_matrix_sync(&Out[m_base * LDS + n_base + 16 * j], acc[j], LDS,
                                wmma::mem_row_major);
}

// 64x128x128 (256 thr): warp grid 2m x 4n, warp tile 32m x 32n (acc[4])
static __device__ __forceinline__ void gemm64_acc(const __half* As, const __half* Wh,
                                                  AccFrag acc[4], int wid) {
    const int m_base = (wid & 1) * 32, n_base = (wid >> 1) * 32;
    #pragma unroll
    for (int i = 0; i < 4; i++) wmma::fill_fragment(acc[i], 0.0f);
    #pragma unroll
    for (int k = 0; k < 8; k++) {
        wmma::fragment<wmma::matrix_a, 16, 16, 16, __half, wmma::row_major> af[2];
        wmma::fragment<wmma::matrix_b, 16, 16, 16, __half, wmma::col_major> bf[2];
        #pragma unroll
        for (int i = 0; i < 2; i++)
            wmma::load_matrix_sync(af[i], &As[(m_base + 16 * i) * LDA + 16 * k], LDA);
        #pragma unroll
        for (int j = 0; j < 2; j++)
            wmma::load_matrix_sync(bf[j], &Wh[(n_base + 16 * j) * LDA + 16 * k], LDA);
        #pragma unroll
        for (int i = 0; i < 2; i++)
            #pragma unroll
            for (int j = 0; j < 2; j++)
                wmma::mma_sync(acc[2 * i + j], af[i], bf[j], acc[2 * i + j]);
    }
}
static __device__ __forceinline__ void store_acc64(AccFrag acc[4], float* Out, int wid) {
    const int m_base = (wid & 1) * 32, n_base = (wid >> 1) * 32;
    #pragma unroll
    for (int i = 0; i < 2; i++)
        #pragma unroll
        for (int j = 0; j < 2; j++)
            wmma::store_matrix_sync(&Out[(m_base + 16 * i) * LDS + n_base + 16 * j],
                                    acc[2 * i + j], LDS, wmma::mem_row_major);
}
static __device__ __forceinline__ void cp_wtile(uint32_t dst, const __half* wsrc, int tid) {
    const char* ws = (const char*)wsrc;
    #pragma unroll
    for (int c = tid; c < 2048; c += 256)
        cp_async16(dst + (c >> 4) * 272 + (c & 15) * 16, ws + (c >> 4) * 256 + (c & 15) * 16);
    cp_commit();
}
static __device__ __forceinline__ void store_A_row(
    __half* dst, int r, int lane, float4 p, float inv)
{
    __half2 h0 = __floats2half2_rn(p.x * inv, p.y * inv);
    __half2 h1 = __floats2half2_rn(p.z * inv, p.w * inv);
    uint2 pk; pk.x = *(uint32_t*)&h0; pk.y = *(uint32_t*)&h1;
    *(uint2*)&dst[r * LDA + 4 * lane] = pk;
}

// non-leaf build: load 4 children's normalized-S (fp16), products + rowmax
static __device__ __forceinline__ void build_products(
    const __half* shin, int node, int b0, int r, int lane,
    float4& p0, float4& p1, float& mx0, float& mx1)
{
    const __half* sp = shin + ((size_t)(4 * node) * BATCH + b0 + r) * KK;
    uint2 qa = ((const uint2*)sp)[lane];
    uint2 qb = ((const uint2*)(sp + BK))[lane];
    uint2 qc = ((const uint2*)(sp + 2 * BK))[lane];
    uint2 qd = ((const uint2*)(sp + 3 * BK))[lane];
    float2 a0 = __half22float2(*(__half2*)&qa.x), a1 = __half22float2(*(__half2*)&qa.y);
    float2 b0f = __half22float2(*(__half2*)&qb.x), b1f = __half22float2(*(__half2*)&qb.y);
    float2 c0 = __half22float2(*(__half2*)&qc.x), c1 = __half22float2(*(__half2*)&qc.y);
    float2 d0 = __half22float2(*(__half2*)&qd.x), d1 = __half22float2(*(__half2*)&qd.y);
    p0.x = a0.x * b0f.x; p0.y = a0.y * b0f.y; p0.z = a1.x * b1f.x; p0.w = a1.y * b1f.y;
    p1.x = c0.x * d0.x;  p1.y = c0.y * d0.y;  p1.z = c1.x * d1.x;  p1.w = c1.y * d1.y;
    mx0 = fmaxf(warp_max(max4(p0)), 1e-35f);
    mx1 = fmaxf(warp_max(max4(p1)), 1e-35f);
}

// ---------------- persistent leaf kernel: one node per block, 4 batch-tiles ----------------
__global__ void __launch_bounds__(256, 2) leaf_persist_kernel(
    const float* __restrict__ x, const float* __restrict__ mu,
    const float* __restrict__ ls)
{
    extern __shared__ char smem[];
    __half* A0s = (__half*)(smem + LP_A0);
    __half* A1s = (__half*)(smem + LP_A1);
    __half* ARs = (__half*)(smem + LP_AR);
    float* S0  = (float*)(smem + LP_S0);
    float* Msum = (float*)(smem + LP_MSUM);
    float* Pm  = (float*)(smem + LP_PM);
    const uint32_t sb = smem_u32(smem);

    const int tid = threadIdx.x, wid = tid >> 5, lane = tid & 31;
    const int node = blockIdx.x;

    const __half* wc0 = g_wh + (size_t)(2 * node) * (KK * KK);
    const __half* wc1 = g_wh + (size_t)(2 * node + 1) * (KK * KK);
    const __half* wup = g_wh + (size_t)(512 + node) * (KK * KK);

    cp_wtile(sb + LP_W0, wc0, tid);
    cp_wtile(sb + LP_W1, wc1, tid);

    // leaf params: once per block
    if (tid < 128) {
        int v0 = 4 * node, v1 = 4 * node + 1, v2 = 4 * node + 2, v3 = 4 * node + 3;
        float l0 = ls[v0 * KK + tid], l1 = ls[v1 * KK + tid];
        float l2 = ls[v2 * KK + tid], l3 = ls[v3 * KK + tid];
        Pm[0 * 128 + tid] = mu[v0 * KK + tid];
        Pm[1 * 128 + tid] = __expf(-l0);
        Pm[2 * 128 + tid] = mu[v1 * KK + tid];
        Pm[3 * 128 + tid] = __expf(-l1);
        Pm[4 * 128 + tid] = -l0 - l1 - 1.8378770664093453f;
        Pm[5 * 128 + tid] = mu[v2 * KK + tid];
        Pm[6 * 128 + tid] = __expf(-l2);
        Pm[7 * 128 + tid] = mu[v3 * KK + tid];
        Pm[8 * 128 + tid] = __expf(-l3);
        Pm[9 * 128 + tid] = -l2 - l3 - 1.8378770664093453f;
    }
    __syncthreads();

    for (int k = 0; k < 4; k++) {
        const int b0 = 64 * k;

        // ---- build both A tiles ----
        #pragma unroll
        for (int it = 0; it < 8; it++) {
            const int r = it * 8 + wid;
            float4 v0, v1;
            float4 xq = *(const float4*)&x[(size_t)(b0 + r) * DD + 4 * node];
            float4 ma0 = *(const float4*)&Pm[0 * 128 + 4 * lane];
            float4 ia0 = *(const float4*)&Pm[1 * 128 + 4 * lane];
            float4 mb0 = *(const float4*)&Pm[2 * 128 + 4 * lane];
            float4 ib0 = *(const float4*)&Pm[3 * 128 + 4 * lane];
            float4 cc0 = *(const float4*)&Pm[4 * 128 + 4 * lane];
            float4 ma1 = *(const float4*)&Pm[5 * 128 + 4 * lane];
            float4 ia1 = *(const float4*)&Pm[6 * 128 + 4 * lane];
            float4 mb1 = *(const float4*)&Pm[7 * 128 + 4 * lane];
            float4 ib1 = *(const float4*)&Pm[8 * 128 + 4 * lane];
            float4 cc1 = *(const float4*)&Pm[9 * 128 + 4 * lane];
            float t, u;
            t = (xq.x - ma0.x) * ia0.x; u = (xq.y - mb0.x) * ib0.x; v0.x = cc0.x - 0.5f * (t*t + u*u);
            t = (xq.x - ma0.y) * ia0.y; u = (xq.y - mb0.y) * ib0.y; v0.y = cc0.y - 0.5f * (t*t + u*u);
            t = (xq.x - ma0.z) * ia0.z; u = (xq.y - mb0.z) * ib0.z; v0.z = cc0.z - 0.5f * (t*t + u*u);
            t = (xq.x - ma0.w) * ia0.w; u = (xq.y - mb0.w) * ib0.w; v0.w = cc0.w - 0.5f * (t*t + u*u);
            t = (xq.z - ma1.x) * ia1.x; u = (xq.w - mb1.x) * ib1.x; v1.x = cc1.x - 0.5f * (t*t + u*u);
            t = (xq.z - ma1.y) * ia1.y; u = (xq.w - mb1.y) * ib1.y; v1.y = cc1.y - 0.5f * (t*t + u*u);
            t = (xq.z - ma1.z) * ia1.z; u = (xq.w - mb1.z) * ib1.z; v1.z = cc1.z - 0.5f * (t*t + u*u);
            t = (xq.z - ma1.w) * ia1.w; u = (xq.w - mb1.w) * ib1.w; v1.w = cc1.w - 0.5f * (t*t + u*u);
            float m0 = warp_max(max4(v0));
            float m1 = warp_max(max4(v1));
            float4 e0, e1;
            e0.x = __expf(v0.x - m0); e0.y = __expf(v0.y - m0);
            e0.z = __expf(v0.z - m0); e0.w = __expf(v0.w - m0);
            e1.x = __expf(v1.x - m1); e1.y = __expf(v1.y - m1);
            e1.z = __expf(v1.z - m1); e1.w = __expf(v1.w - m1);
            store_A_row(A0s, r, lane, e0, 1.0f);
            store_A_row(A1s, r, lane, e1, 1.0f);
            if (lane == 0) Msum[r] = m0 + m1;
        }

        AccFrag acc1[4], acc2[4];

        cp_wait<0>();        // item0: Wc0+Wc1; items>0: Wc0 reload
        __syncthreads();

        gemm64_acc(A0s, (const __half*)(smem + LP_W0), acc1, wid);
        gemm64_acc(A1s, (const __half*)(smem + LP_W1), acc2, wid);

        #pragma unroll
        for (int i = 0; i < 4; i++)
            #pragma unroll
            for (int e = 0; e < acc2[i].num_elements; e++)
                acc2[i].x[e] *= acc1[i].x[e];

        __syncthreads();                         // done reading W0 & A tiles
        cp_wtile(sb + LP_W0, wup, tid);          // W_up -> W0 slot
        store_acc64(acc2, S0, wid);
        __syncthreads();                         // S0 visible

        // ---- renorm: stage in regs (S0 aliases AR target region) ----
        uint2 arreg[8];
        #pragma unroll
        for (int it = 0; it < 8; it++) {
            const int r = it * 8 + wid;
            float4 p = *(const float4*)&S0[r * LDS + 4 * lane];
            float pmax = fmaxf(warp_max(max4(p)), 1e-35f);
            float inv = __fdividef(1.0f, pmax);
            __half2 h0 = __floats2half2_rn(p.x * inv, p.y * inv);
            __half2 h1 = __floats2half2_rn(p.z * inv, p.w * inv);
            arreg[it].x = *(uint32_t*)&h0; arreg[it].y = *(uint32_t*)&h1;
            if (lane == 0) Msum[r] += __logf(pmax);
        }
        cp_wait<0>();        // W_up ready
        __syncthreads();     // ALL warps done reading S0 -> safe to clobber with AR
        #pragma unroll
        for (int it = 0; it < 8; it++)
            *(uint2*)&ARs[(it * 8 + wid) * LDA + 4 * lane] = arreg[it];
        __syncthreads();     // AR visible

        gemm64_acc(ARs, (const __half*)(smem + LP_W0), acc1, wid);
        __syncthreads();     // all warps done reading AR/W0 before overwrite

        if (k < 3) cp_wtile(sb + LP_W0, wc0, tid);   // reload Wc0 (L2 hit) for next item
        store_acc64(acc1, S0, wid);
        __syncthreads();

        // ---- epilogue: normalized fp16 S + M ----
        {
            const int r = tid >> 2, cg = tid & 3, c0 = cg * 32;
            float vmax = 0.0f;
            #pragma unroll
            for (int c = 0; c < 8; c++) {
                float4 s = *(const float4*)&S0[r * LDS + c0 + 4 * c];
                vmax = fmaxf(vmax, max4(s));
            }
            vmax = fmaxf(vmax, __shfl_xor_sync(0xffffffffu, vmax, 1));
            vmax = fmaxf(vmax, __shfl_xor_sync(0xffffffffu, vmax, 2));
            vmax = fmaxf(vmax, 1e-35f);
            const float inv = __fdividef(1.0f, vmax);
            __half* orow = g_sh0 + ((size_t)node * BATCH + b0 + r) * KK + c0;
            #pragma unroll
            for (int q = 0; q < 4; q++) {
                float4 s0 = *(const float4*)&S0[r * LDS + c0 + 8 * q];
                float4 s1 = *(const float4*)&S0[r * LDS + c0 + 8 * q + 4];
                __half2 h0 = __floats2half2_rn(s0.x * inv, s0.y * inv);
                __half2 h1 = __floats2half2_rn(s0.z * inv, s0.w * inv);
                __half2 h2 = __floats2half2_rn(s1.x * inv, s1.y * inv);
                __half2 h3 = __floats2half2_rn(s1.z * inv, s1.w * inv);
                uint4 pk;
                pk.x = *(uint32_t*)&h0; pk.y = *(uint32_t*)&h1;
                pk.z = *(uint32_t*)&h2; pk.w = *(uint32_t*)&h3;
                *(uint4*)(orow + 8 * q) = pk;
            }
            if (cg == 0) g_m0[(size_t)node * BATCH + b0 + r] = Msum[r] + __logf(vmax);
        }
        __syncthreads();     // S0/Msum reuse next item
    }
}

// ---------------- pair64 (non-leaf, 64 rows, 256 thr) ----------------
__global__ void __launch_bounds__(256, 2) pair64_kernel(
    int insel, int outsel, int wlo, int wup)
{
    extern __shared__ char smem[];
    __half* A0s = (__half*)(smem + P64_A0);
    __half* A1s = (__half*)(smem + P64_A1);
    __half* ARs = (__half*)(smem + P64_AR);
    float* S0  = (float*)(smem + P64_S0);
    float* Msum = (float*)(smem + P64_MSUM);
    const uint32_t sb = smem_u32(smem);

    const int tid = threadIdx.x, wid = tid >> 5, lane = tid & 31;
    const int node = blockIdx.y;
    const int b0 = blockIdx.x * 64;

    const __half* shin = (insel == 0) ? g_sh0 : g_sh1;
    const float* minb  = (insel == 0) ? g_m0  : g_m1;
    __half* shout = (outsel == 0) ? g_sh0 : g_sh1;
    float* mout   = (outsel == 0) ? g_m0  : g_m1;

    cp_wtile(sb + P64_W0, g_wh + (size_t)(wlo + 2 * node) * (KK * KK), tid);
    cp_wtile(sb + P64_W1, g_wh + (size_t)(wlo + 2 * node + 1) * (KK * KK), tid);

    #pragma unroll
    for (int it = 0; it < 8; it++) {
        const int r = it * 8 + wid;
        float4 p0, p1; float mx0, mx1;
        build_products(shin, node, b0, r, lane, p0, p1, mx0, mx1);
        store_A_row(A0s, r, lane, p0, __fdividef(1.0f, mx0));
        store_A_row(A1s, r, lane, p1, __fdividef(1.0f, mx1));
        if (lane == 0) {
            float Ma = minb[(size_t)(4 * node + 0) * BATCH + b0 + r];
            float Mb = minb[(size_t)(4 * node + 1) * BATCH + b0 + r];
            float Mc = minb[(size_t)(4 * node + 2) * BATCH + b0 + r];
            float Md = minb[(size_t)(4 * node + 3) * BATCH + b0 + r];
            Msum[r] = Ma + Mb + Mc + Md + __logf(mx0) + __logf(mx1);
        }
    }

    AccFrag acc1[4], acc2[4];

    cp_wait<0>();
    __syncthreads();

    gemm64_acc(A0s, (const __half*)(smem + P64_W0), acc1, wid);
    gemm64_acc(A1s, (const __half*)(smem + P64_W1), acc2, wid);

    #pragma unroll
    for (int i = 0; i < 4; i++)
        #pragma unroll
        for (int e = 0; e < acc2[i].num_elements; e++)
            acc2[i].x[e] *= acc1[i].x[e];

    __syncthreads();
    cp_wtile(sb + P64_W0, g_wh + (size_t)(wup + node) * (KK * KK), tid);
    store_acc64(acc2, S0, wid);
    __syncthreads();

    #pragma unroll
    for (int it = 0; it < 8; it++) {
        const int r = it * 8 + wid;
        float4 p = *(const float4*)&S0[r * LDS + 4 * lane];
        float pmax = fmaxf(warp_max(max4(p)), 1e-35f);
        store_A_row(ARs, r, lane, p, __fdividef(1.0f, pmax));
        if (lane == 0) Msum[r] += __logf(pmax);
    }

    cp_wait<0>();
    __syncthreads();
    gemm64_acc(ARs, (const __half*)(smem + P64_W0), acc1, wid);
    store_acc64(acc1, S0, wid);
    __syncthreads();

    {
        const int r = tid >> 2, cg = tid & 3, c0 = cg * 32;
        float vmax = 0.0f;
        #pragma unroll
        for (int c = 0; c < 8; c++) {
            float4 s = *(const float4*)&S0[r * LDS + c0 + 4 * c];
            vmax = fmaxf(vmax, max4(s));
        }
        vmax = fmaxf(vmax, __shfl_xor_sync(0xffffffffu, vmax, 1));
        vmax = fmaxf(vmax, __shfl_xor_sync(0xffffffffu, vmax, 2));
        vmax = fmaxf(vmax, 1e-35f);
        const float inv = __fdividef(1.0f, vmax);
        __half* orow = shout + ((size_t)node * BATCH + b0 + r) * KK + c0;
        #pragma unroll
        for (int q = 0; q < 4; q++) {
            float4 s0 = *(const float4*)&S0[r * LDS + c0 + 8 * q];
            float4 s1 = *(const float4*)&S0[r * LDS + c0 + 8 * q + 4];
            __half2 h0 = __floats2half2_rn(s0.x * inv, s0.y * inv);
            __half2 h1 = __floats2half2_rn(s0.z * inv, s0.w * inv);
            __half2 h2 = __floats2half2_rn(s1.x * inv, s1.y * inv);
            __half2 h3 = __floats2half2_rn(s1.z * inv, s1.w * inv);
            uint4 pk;
            pk.x = *(uint32_t*)&h0; pk.y = *(uint32_t*)&h1;
            pk.z = *(uint32_t*)&h2; pk.w = *(uint32_t*)&h3;
            *(uint4*)(orow + 8 * q) = pk;
        }
        if (cg == 0) mout[(size_t)node * BATCH + b0 + r] = Msum[r] + __logf(vmax);
    }
}

// ---------------- pair32 (small levels) ----------------
template<bool FINAL>
__global__ void __launch_bounds__(256, 2) pair32_kernel(
    int insel, int outsel, int wlo, int wup, float* __restrict__ dout)
{
    extern __shared__ char smem[];
    __half* As = (__half*)(smem + SM_A);
    float* S0  = (float*)(smem + SM_S0);
    float* Msum = (float*)(smem + SM_MSUM);
    const uint32_t sb = smem_u32(smem);

    const int tid = threadIdx.x, wid = tid >> 5, lane = tid & 31;
    const int node = blockIdx.y;
    const int b0 = blockIdx.x * 32;

    const __half* shin = (insel == 0) ? g_sh0 : g_sh1;
    const float* minb  = (insel == 0) ? g_m0  : g_m1;
    __half* shout = (outsel == 0) ? g_sh0 : g_sh1;
    float* mout   = (outsel == 0) ? g_m0  : g_m1;

    cp_wtile(sb + SM_W0, g_wh + (size_t)(wlo + 2 * node) * (KK * KK), tid);
    cp_wtile(sb + SM_W1, g_wh + (size_t)(wlo + 2 * node + 1) * (KK * KK), tid);

    float4 p1r[4];
    float mx1r[4];
    #pragma unroll
    for (int it = 0; it < 4; it++) {
        const int r = it * 8 + wid;
        float4 p0, p1; float mx0, mx1;
        build_products(shin, node, b0, r, lane, p0, p1, mx0, mx1);
        store_A_row(As, r, lane, p0, __fdividef(1.0f, mx0));
        p1r[it] = p1; mx1r[it] = mx1;
        if (lane == 0) {
            float Ma = minb[(size_t)(4 * node + 0) * BATCH + b0 + r];
            float Mb = minb[(size_t)(4 * node + 1) * BATCH + b0 + r];
            float Mc = minb[(size_t)(4 * node + 2) * BATCH + b0 + r];
            float Md = minb[(size_t)(4 * node + 3) * BATCH + b0 + r];
            Msum[r] = Ma + Mb + Mc + Md + __logf(mx0) + __logf(mx1);
        }
    }

    AccFrag acc1[2], acc2[2];

    cp_wait<1>();
    __syncthreads();
    gemm32_acc(As, (const __half*)(smem + SM_W0), acc1, wid);
    __syncthreads();

    cp_wtile(sb + SM_W0, g_wh + (size_t)(wup + node) * (KK * KK), tid);

    #pragma unroll
    for (int it = 0; it < 4; it++)
        store_A_row(As, it * 8 + wid, lane, p1r[it], __fdividef(1.0f, mx1r[it]));

    cp_wait<1>();
    __syncthreads();
    gemm32_acc(As, (const __half*)(smem + SM_W1), acc2, wid);

    #pragma unroll
    for (int j = 0; j < 2; j++)
        #pragma unroll
        for (int e = 0; e < acc2[j].num_elements; e++)
            acc2[j].x[e] *= acc1[j].x[e];
    store_acc32(acc2, S0, wid);
    __syncthreads();

    #pragma unroll
    for (int it = 0; it < 4; it++) {
        const int r = it * 8 + wid;
        float4 p = *(const float4*)&S0[r * LDS + 4 * lane];
        float pmax = fmaxf(warp_max(max4(p)), 1e-35f);
        store_A_row(As, r, lane, p, __fdividef(1.0f, pmax));
        if (lane == 0) Msum[r] += __logf(pmax);
    }

    cp_wait<0>();
    __syncthreads();
    gemm32_acc(As, (const __half*)(smem + SM_W0), acc2, wid);
    store_acc32(acc2, S0, wid);
    __syncthreads();

    if (FINAL) {
        const int r = tid >> 3, c0 = (tid & 7) * 16;
        const float mrow = Msum[r];
        float* orow = dout + ((size_t)node * BATCH + b0 + r) * KK + c0;
        #pragma unroll
        for (int c = 0; c < 4; c++) {
            float4 s = *(const float4*)&S0[r * LDS + c0 + 4 * c];
            float4 o;
            o.x = mrow + __logf(s.x); o.y = mrow + __logf(s.y);
            o.z = mrow + __logf(s.z); o.w = mrow + __logf(s.w);
            ((float4*)orow)[c] = o;
        }
    } else {
        const int r = tid >> 3, cg = tid & 7, c0 = cg * 16;
        float vmax = 0.0f;
        #pragma unroll
        for (int c = 0; c < 4; c++) {
            float4 s = *(const float4*)&S0[r * LDS + c0 + 4 * c];
            vmax = fmaxf(vmax, max4(s));
        }
        vmax = fmaxf(vmax, __shfl_xor_sync(0xffffffffu, vmax, 1));
        vmax = fmaxf(vmax, __shfl_xor_sync(0xffffffffu, vmax, 2));
        vmax = fmaxf(vmax, __shfl_xor_sync(0xffffffffu, vmax, 4));
        vmax = fmaxf(vmax, 1e-35f);
        const float inv = __fdividef(1.0f, vmax);
        __half* orow = shout + ((size_t)node * BATCH + b0 + r) * KK + c0;
        #pragma unroll
        for (int q = 0; q < 2; q++) {
            float4 s0 = *(const float4*)&S0[r * LDS + c0 + 8 * q];
            float4 s1 = *(const float4*)&S0[r * LDS + c0 + 8 * q + 4];
            __half2 h0 = __floats2half2_rn(s0.x * inv, s0.y * inv);
            __half2 h1 = __floats2half2_rn(s0.z * inv, s0.w * inv);
            __half2 h2 = __floats2half2_rn(s1.x * inv, s1.y * inv);
            __half2 h3 = __floats2half2_rn(s1.z * inv, s1.w * inv);
            uint4 pk;
            pk.x = *(uint32_t*)&h0; pk.y = *(uint32_t*)&h1;
            pk.z = *(uint32_t*)&h2; pk.w = *(uint32_t*)&h3;
            *(uint4*)(orow + 8 * q) = pk;
        }
        if (cg == 0) mout[(size_t)node * BATCH + b0 + r] = Msum[r] + __logf(vmax);
    }
}

extern "C" void kernel_launch(void* const* d_in, const int* in_sizes, int n_in,
                              void* d_out, int out_size) {
    const float* x  = (const float*)d_in[0];
    const float* mu = (const float*)d_in[1];
    const float* ls = (const float*)d_in[2];
    const float* w  = (const float*)d_in[3];
    float* out = (float*)d_out;

    cudaFuncSetAttribute(leaf_persist_kernel, cudaFuncAttributeMaxDynamicSharedMemorySize, LP_BYTES);
    cudaFuncSetAttribute(pair64_kernel, cudaFuncAttributeMaxDynamicSharedMemorySize, P64_BYTES);
    cudaFuncSetAttribute(pair32_kernel<false>, cudaFuncAttributeMaxDynamicSharedMemorySize, SMEM_BYTES);
    cudaFuncSetAttribute(pair32_kernel<true>,  cudaFuncAttributeMaxDynamicSharedMemorySize, SMEM_BYTES);

    softmax_w_kernel<<<1023, 256>>>(w);

    leaf_persist_kernel<<<256, 256, LP_BYTES>>>(x, mu, ls);                // (leaf512+256) -> sh0
    pair64_kernel<<<dim3(4, 64), 256, P64_BYTES>>>(0, 1, 768, 896);        // (128+64) -> sh1
    pair32_kernel<false><<<dim3(8, 16), 256, SMEM_BYTES>>>(1, 0, 960,  992,  out); // -> sh0
    pair32_kernel<false><<<dim3(8, 4),  256, SMEM_BYTES>>>(0, 1, 1008, 1016, out); // -> sh1
    pair32_kernel<true ><<<dim3(8, 1),  256, SMEM_BYTES>>>(1, 2, 1020, 1022, out); // -> out
}

// round 16
// speedup vs baseline: 1.0342x; 1.0342x over previous
#include <cuda_runtime.h>
#include <cuda_fp16.h>
#include <mma.h>
#include <stdint.h>

using namespace nvcuda;

#define KK 128
#define BATCH 256
#define DD 1024
#define BK (BATCH*KK)
#define LDA 136           // halves per A/W smem row (272 B)
#define LDS 132           // floats per S smem row

// static scratch (allocation-free rule)
__device__ __half g_sh0[256 * BATCH * KK];
__device__ __half g_sh1[64 * BATCH * KK];
__device__ float  g_m0[256 * BATCH];
__device__ float  g_m1[64 * BATCH];
__device__ __half g_wh[1023 * KK * KK];      // softmax(W) fp16

// ---- pair32 smem layout ----
#define SM_W0   0
#define SM_W1   34816
#define SM_A    69632
#define SM_S0   78336
#define SM_MSUM 95232
#define SMEM_BYTES (SM_MSUM + 192)

// ---- pair64 smem layout (64 rows, 256 thr) ----
#define P64_W0   0
#define P64_W1   34816
#define P64_AR   34816      // alias of W1 (renormalized A after GEMM2)
#define P64_A0   69632
#define P64_A1   87040
#define P64_S0   69632      // alias A0+A1
#define P64_MSUM 104448
#define P64_PM   104704     // leaf params 10x128 f32
#define P64_BYTES (P64_PM + 5120 + 64)   // ~107.3 KB -> 2 blocks/SM

// ---------------- helpers ----------------
static __device__ __forceinline__ uint32_t smem_u32(const void* p) {
    uint32_t a;
    asm("{ .reg .u64 t; cvta.to.shared.u64 t, %1; cvt.u32.u64 %0, t; }" : "=r"(a) : "l"(p));
    return a;
}
static __device__ __forceinline__ void cp_async16(uint32_t dst, const void* src) {
    asm volatile("cp.async.cg.shared.global [%0], [%1], 16;" :: "r"(dst), "l"(src));
}
static __device__ __forceinline__ void cp_commit() {
    asm volatile("cp.async.commit_group;" ::: "memory");
}
template<int N> static __device__ __forceinline__ void cp_wait() {
    asm volatile("cp.async.wait_group %0;" :: "n"(N) : "memory");
}
static __device__ __forceinline__ float warp_max(float m) {
    #pragma unroll
    for (int o = 16; o; o >>= 1) m = fmaxf(m, __shfl_xor_sync(0xffffffffu, m, o));
    return m;
}
static __device__ __forceinline__ float max4(float4 v) {
    return fmaxf(fmaxf(v.x, v.y), fmaxf(v.z, v.w));
}
// power-of-two renorm: inv = 2^(127-E), logadd = (E-127)*ln2 (exact)
static __device__ __forceinline__ float pow2_inv(float pmax, float& logadd) {
    uint32_t E = __float_as_uint(pmax) >> 23;     // pmax clamped positive normal
    logadd = (float)((int)E - 127) * 0.6931471805599453f;
    return __uint_as_float((254u - E) << 23);
}

// ---------------- K0: softmax(W) -> fp16 ----------------
__global__ void __launch_bounds__(256) softmax_w_kernel(const float* __restrict__ w) {
    const int node = blockIdx.x;
    const int wid = threadIdx.x >> 5, lane = threadIdx.x & 31;
    const float* wn = w + (size_t)node * (KK * KK);
    __half* out = g_wh + (size_t)node * (KK * KK);
    #pragma unroll 4
    for (int i = wid; i < KK; i += 8) {
        float4 v = ((const float4*)(wn + i * KK))[lane];
        float m = warp_max(max4(v));
        float e0 = __expf(v.x - m), e1 = __expf(v.y - m);
        float e2 = __expf(v.z - m), e3 = __expf(v.w - m);
        float s = e0 + e1 + e2 + e3;
        #pragma unroll
        for (int o = 16; o; o >>= 1) s += __shfl_xor_sync(0xffffffffu, s, o);
        float inv = 1.0f / s;
        __half2 h0 = __floats2half2_rn(e0 * inv, e1 * inv);
        __half2 h1 = __floats2half2_rn(e2 * inv, e3 * inv);
        uint2 pk; pk.x = *(uint32_t*)&h0; pk.y = *(uint32_t*)&h1;
        *(uint2*)&out[i * KK + 4 * lane] = pk;
    }
}

using AccFrag = wmma::fragment<wmma::accumulator, 16, 16, 16, float>;

// 32x128x128: warp tile 16m x 32n
static __device__ __forceinline__ void gemm32_acc(const __half* As, const __half* Wh,
                                                  AccFrag acc[2], int wid) {
    const int m_base = (wid & 1) * 16, n_base = (wid >> 1) * 32;
    wmma::fill_fragment(acc[0], 0.0f);
    wmma::fill_fragment(acc[1], 0.0f);
    #pragma unroll
    for (int k = 0; k < 8; k++) {
        wmma::fragment<wmma::matrix_a, 16, 16, 16, __half, wmma::row_major> af;
        wmma::load_matrix_sync(af, &As[m_base * LDA + 16 * k], LDA);
        #pragma unroll
        for (int j = 0; j < 2; j++) {
            wmma::fragment<wmma::matrix_b, 16, 16, 16, __half, wmma::col_major> bf;
            wmma::load_matrix_sync(bf, &Wh[(n_base + 16 * j) * LDA + 16 * k], LDA);
            wmma::mma_sync(acc[j], af, bf, acc[j]);
        }
    }
}
static __device__ __forceinline__ void store_acc32(AccFrag acc[2], float* Out, int wid) {
    const int m_base = (wid & 1) * 16, n_base = (wid >> 1) * 32;
    #pragma unroll
    for (int j = 0; j < 2; j++)
        wmma::store_matrix_sync(&Out[m_base * LDS + n_base + 16 * j], acc[j], LDS,
                                wmma::mem_row_major);
}

// 64x128x128 (256 thr): warp grid 2m x 4n, warp tile 32m x 32n (acc[4])
static __device__ __forceinline__ void gemm64_acc(const __half* As, const __half* Wh,
                                                  AccFrag acc[4], int wid) {
    const int m_base = (wid & 1) * 32, n_base = (wid >> 1) * 32;
    #pragma unroll
    for (int i = 0; i < 4; i++) wmma::fill_fragment(acc[i], 0.0f);
    #pragma unroll
    for (int k = 0; k < 8; k++) {
        wmma::fragment<wmma::matrix_a, 16, 16, 16, __half, wmma::row_major> af[2];
        wmma::fragment<wmma::matrix_b, 16, 16, 16, __half, wmma::col_major> bf[2];
        #pragma unroll
        for (int i = 0; i < 2; i++)
            wmma::load_matrix_sync(af[i], &As[(m_base + 16 * i) * LDA + 16 * k], LDA);
        #pragma unroll
        for (int j = 0; j < 2; j++)
            wmma::load_matrix_sync(bf[j], &Wh[(n_base + 16 * j) * LDA + 16 * k], LDA);
        #pragma unroll
        for (int i = 0; i < 2; i++)
            #pragma unroll
            for (int j = 0; j < 2; j++)
                wmma::mma_sync(acc[2 * i + j], af[i], bf[j], acc[2 * i + j]);
    }
}
static __device__ __forceinline__ void store_acc64(AccFrag acc[4], float* Out, int wid) {
    const int m_base = (wid & 1) * 32, n_base = (wid >> 1) * 32;
    #pragma unroll
    for (int i = 0; i < 2; i++)
        #pragma unroll
        for (int j = 0; j < 2; j++)
            wmma::store_matrix_sync(&Out[(m_base + 16 * i) * LDS + n_base + 16 * j],
                                    acc[2 * i + j], LDS, wmma::mem_row_major);
}
static __device__ __forceinline__ void cp_wtile(uint32_t dst, const __half* wsrc, int tid) {
    const char* ws = (const char*)wsrc;
    #pragma unroll
    for (int c = tid; c < 2048; c += 256)
        cp_async16(dst + (c >> 4) * 272 + (c & 15) * 16, ws + (c >> 4) * 256 + (c & 15) * 16);
    cp_commit();
}
static __device__ __forceinline__ void store_A_row(
    __half* dst, int r, int lane, float4 p, float inv)
{
    __half2 h0 = __floats2half2_rn(p.x * inv, p.y * inv);
    __half2 h1 = __floats2half2_rn(p.z * inv, p.w * inv);
    uint2 pk; pk.x = *(uint32_t*)&h0; pk.y = *(uint32_t*)&h1;
    *(uint2*)&dst[r * LDA + 4 * lane] = pk;
}

// non-leaf build: load 4 children's normalized-S (fp16), products + rowmax
static __device__ __forceinline__ void build_products(
    const __half* shin, int node, int b0, int r, int lane,
    float4& p0, float4& p1, float& mx0, float& mx1)
{
    const __half* sp = shin + ((size_t)(4 * node) * BATCH + b0 + r) * KK;
    uint2 qa = ((const uint2*)sp)[lane];
    uint2 qb = ((const uint2*)(sp + BK))[lane];
    uint2 qc = ((const uint2*)(sp + 2 * BK))[lane];
    uint2 qd = ((const uint2*)(sp + 3 * BK))[lane];
    float2 a0 = __half22float2(*(__half2*)&qa.x), a1 = __half22float2(*(__half2*)&qa.y);
    float2 b0f = __half22float2(*(__half2*)&qb.x), b1f = __half22float2(*(__half2*)&qb.y);
    float2 c0 = __half22float2(*(__half2*)&qc.x), c1 = __half22float2(*(__half2*)&qc.y);
    float2 d0 = __half22float2(*(__half2*)&qd.x), d1 = __half22float2(*(__half2*)&qd.y);
    p0.x = a0.x * b0f.x; p0.y = a0.y * b0f.y; p0.z = a1.x * b1f.x; p0.w = a1.y * b1f.y;
    p1.x = c0.x * d0.x;  p1.y = c0.y * d0.y;  p1.z = c1.x * d1.x;  p1.w = c1.y * d1.y;
    mx0 = fmaxf(warp_max(max4(p0)), 1e-35f);
    mx1 = fmaxf(warp_max(max4(p1)), 1e-35f);
}

// ---------------- pair64: 64-row blocks, 256 threads ----------------
template<bool LEAF>
__global__ void __launch_bounds__(256, 2) pair64_kernel(
    int insel, int outsel, int wlo, int wup,
    const float* __restrict__ x, const float* __restrict__ mu,
    const float* __restrict__ ls)
{
    extern __shared__ char smem[];
    __half* A0s = (__half*)(smem + P64_A0);
    __half* A1s = (__half*)(smem + P64_A1);
    __half* ARs = (__half*)(smem + P64_AR);
    float* S0  = (float*)(smem + P64_S0);
    float* Msum = (float*)(smem + P64_MSUM);
    float* Pm  = (float*)(smem + P64_PM);
    const uint32_t sb = smem_u32(smem);

    const int tid = threadIdx.x, wid = tid >> 5, lane = tid & 31;
    const int node = blockIdx.y;
    const int b0 = blockIdx.x * 64;

    const __half* shin = (insel == 0) ? g_sh0 : g_sh1;
    const float* minb  = (insel == 0) ? g_m0  : g_m1;
    __half* shout = (outsel == 0) ? g_sh0 : g_sh1;
    float* mout   = (outsel == 0) ? g_m0  : g_m1;

    cp_wtile(sb + P64_W0, g_wh + (size_t)(wlo + 2 * node) * (KK * KK), tid);
    cp_wtile(sb + P64_W1, g_wh + (size_t)(wlo + 2 * node + 1) * (KK * KK), tid);

    if (LEAF) {
        if (tid < 128) {
            int v0 = 4 * node, v1 = 4 * node + 1, v2 = 4 * node + 2, v3 = 4 * node + 3;
            float l0 = ls[v0 * KK + tid], l1 = ls[v1 * KK + tid];
            float l2 = ls[v2 * KK + tid], l3 = ls[v3 * KK + tid];
            Pm[0 * 128 + tid] = mu[v0 * KK + tid];
            Pm[1 * 128 + tid] = __expf(-l0);
            Pm[2 * 128 + tid] = mu[v1 * KK + tid];
            Pm[3 * 128 + tid] = __expf(-l1);
            Pm[4 * 128 + tid] = -l0 - l1 - 1.8378770664093453f;
            Pm[5 * 128 + tid] = mu[v2 * KK + tid];
            Pm[6 * 128 + tid] = __expf(-l2);
            Pm[7 * 128 + tid] = mu[v3 * KK + tid];
            Pm[8 * 128 + tid] = __expf(-l3);
            Pm[9 * 128 + tid] = -l2 - l3 - 1.8378770664093453f;
        }
        __syncthreads();
    }

    // ---- build BOTH A tiles (8 rows per warp) ----
    #pragma unroll
    for (int it = 0; it < 8; it++) {
        const int r = it * 8 + wid;
        if (LEAF) {
            float4 v0, v1;
            float4 xq = *(const float4*)&x[(size_t)(b0 + r) * DD + 4 * node];
            float4 ma0 = *(const float4*)&Pm[0 * 128 + 4 * lane];
            float4 ia0 = *(const float4*)&Pm[1 * 128 + 4 * lane];
            float4 mb0 = *(const float4*)&Pm[2 * 128 + 4 * lane];
            float4 ib0 = *(const float4*)&Pm[3 * 128 + 4 * lane];
            float4 cc0 = *(const float4*)&Pm[4 * 128 + 4 * lane];
            float4 ma1 = *(const float4*)&Pm[5 * 128 + 4 * lane];
            float4 ia1 = *(const float4*)&Pm[6 * 128 + 4 * lane];
            float4 mb1 = *(const float4*)&Pm[7 * 128 + 4 * lane];
            float4 ib1 = *(const float4*)&Pm[8 * 128 + 4 * lane];
            float4 cc1 = *(const float4*)&Pm[9 * 128 + 4 * lane];
            float t, u;
            t = (xq.x - ma0.x) * ia0.x; u = (xq.y - mb0.x) * ib0.x; v0.x = cc0.x - 0.5f * (t*t + u*u);
            t = (xq.x - ma0.y) * ia0.y; u = (xq.y - mb0.y) * ib0.y; v0.y = cc0.y - 0.5f * (t*t + u*u);
            t = (xq.x - ma0.z) * ia0.z; u = (xq.y - mb0.z) * ib0.z; v0.z = cc0.z - 0.5f * (t*t + u*u);
            t = (xq.x - ma0.w) * ia0.w; u = (xq.y - mb0.w) * ib0.w; v0.w = cc0.w - 0.5f * (t*t + u*u);
            t = (xq.z - ma1.x) * ia1.x; u = (xq.w - mb1.x) * ib1.x; v1.x = cc1.x - 0.5f * (t*t + u*u);
            t = (xq.z - ma1.y) * ia1.y; u = (xq.w - mb1.y) * ib1.y; v1.y = cc1.y - 0.5f * (t*t + u*u);
            t = (xq.z - ma1.z) * ia1.z; u = (xq.w - mb1.z) * ib1.z; v1.z = cc1.z - 0.5f * (t*t + u*u);
            t = (xq.z - ma1.w) * ia1.w; u = (xq.w - mb1.w) * ib1.w; v1.w = cc1.w - 0.5f * (t*t + u*u);
            float m0 = warp_max(max4(v0));
            float m1 = warp_max(max4(v1));
            float4 e0, e1;
            e0.x = __expf(v0.x - m0); e0.y = __expf(v0.y - m0);
            e0.z = __expf(v0.z - m0); e0.w = __expf(v0.w - m0);
            e1.x = __expf(v1.x - m1); e1.y = __expf(v1.y - m1);
            e1.z = __expf(v1.z - m1); e1.w = __expf(v1.w - m1);
            store_A_row(A0s, r, lane, e0, 1.0f);
            store_A_row(A1s, r, lane, e1, 1.0f);
            if (lane == 0) Msum[r] = m0 + m1;
        } else {
            float4 p0, p1; float mx0, mx1;
            build_products(shin, node, b0, r, lane, p0, p1, mx0, mx1);
            float l0, l1;
            float i0 = pow2_inv(mx0, l0);
            float i1 = pow2_inv(mx1, l1);
            store_A_row(A0s, r, lane, p0, i0);
            store_A_row(A1s, r, lane, p1, i1);
            if (lane == 0) {
                float Ma = minb[(size_t)(4 * node + 0) * BATCH + b0 + r];
                float Mb = minb[(size_t)(4 * node + 1) * BATCH + b0 + r];
                float Mc = minb[(size_t)(4 * node + 2) * BATCH + b0 + r];
                float Md = minb[(size_t)(4 * node + 3) * BATCH + b0 + r];
                Msum[r] = Ma + Mb + Mc + Md + l0 + l1;
            }
        }
    }

    AccFrag acc1[4], acc2[4];

    cp_wait<0>();            // W_c0 + W_c1 ready
    __syncthreads();

    gemm64_acc(A0s, (const __half*)(smem + P64_W0), acc1, wid);
    gemm64_acc(A1s, (const __half*)(smem + P64_W1), acc2, wid);

    #pragma unroll
    for (int i = 0; i < 4; i++)
        #pragma unroll
        for (int e = 0; e < acc2[i].num_elements; e++)
            acc2[i].x[e] *= acc1[i].x[e];

    __syncthreads();
    cp_wtile(sb + P64_W0, g_wh + (size_t)(wup + node) * (KK * KK), tid);   // W_up -> W0
    store_acc64(acc2, S0, wid);
    __syncthreads();

    // ---- renorm -> ARs (pow2 scale), Msum += k*ln2 ----
    #pragma unroll
    for (int it = 0; it < 8; it++) {
        const int r = it * 8 + wid;
        float4 p = *(const float4*)&S0[r * LDS + 4 * lane];
        float pmax = fmaxf(warp_max(max4(p)), 1e-35f);
        float la;
        float inv = pow2_inv(pmax, la);
        store_A_row(ARs, r, lane, p, inv);
        if (lane == 0) Msum[r] += la;
    }

    cp_wait<0>();            // W_up ready
    __syncthreads();
    gemm64_acc(ARs, (const __half*)(smem + P64_W0), acc1, wid);
    store_acc64(acc1, S0, wid);
    __syncthreads();

    // ---- epilogue: normalized fp16 S + M ----
    {
        const int r = tid >> 2, cg = tid & 3, c0 = cg * 32;
        float vmax = 0.0f;
        #pragma unroll
        for (int c = 0; c < 8; c++) {
            float4 s = *(const float4*)&S0[r * LDS + c0 + 4 * c];
            vmax = fmaxf(vmax, max4(s));
        }
        vmax = fmaxf(vmax, __shfl_xor_sync(0xffffffffu, vmax, 1));
        vmax = fmaxf(vmax, __shfl_xor_sync(0xffffffffu, vmax, 2));
        vmax = fmaxf(vmax, 1e-35f);
        float lv;
        const float inv = pow2_inv(vmax, lv);
        __half* orow = shout + ((size_t)node * BATCH + b0 + r) * KK + c0;
        #pragma unroll
        for (int q = 0; q < 4; q++) {
            float4 s0 = *(const float4*)&S0[r * LDS + c0 + 8 * q];
            float4 s1 = *(const float4*)&S0[r * LDS + c0 + 8 * q + 4];
            __half2 h0 = __floats2half2_rn(s0.x * inv, s0.y * inv);
            __half2 h1 = __floats2half2_rn(s0.z * inv, s0.w * inv);
            __half2 h2 = __floats2half2_rn(s1.x * inv, s1.y * inv);
            __half2 h3 = __floats2half2_rn(s1.z * inv, s1.w * inv);
            uint4 pk;
            pk.x = *(uint32_t*)&h0; pk.y = *(uint32_t*)&h1;
            pk.z = *(uint32_t*)&h2; pk.w = *(uint32_t*)&h3;
            *(uint4*)(orow + 8 * q) = pk;
        }
        if (cg == 0) mout[(size_t)node * BATCH + b0 + r] = Msum[r] + lv;
    }
}

// ---------------- pair32 (root level, FINAL epilogue) ----------------
template<bool FINAL>
__global__ void __launch_bounds__(256, 2) pair32_kernel(
    int insel, int outsel, int wlo, int wup, float* __restrict__ dout)
{
    extern __shared__ char smem[];
    __half* As = (__half*)(smem + SM_A);
    float* S0  = (float*)(smem + SM_S0);
    float* Msum = (float*)(smem + SM_MSUM);
    const uint32_t sb = smem_u32(smem);

    const int tid = threadIdx.x, wid = tid >> 5, lane = tid & 31;
    const int node = blockIdx.y;
    const int b0 = blockIdx.x * 32;

    const __half* shin = (insel == 0) ? g_sh0 : g_sh1;
    const float* minb  = (insel == 0) ? g_m0  : g_m1;
    __half* shout = (outsel == 0) ? g_sh0 : g_sh1;
    float* mout   = (outsel == 0) ? g_m0  : g_m1;

    cp_wtile(sb + SM_W0, g_wh + (size_t)(wlo + 2 * node) * (KK * KK), tid);
    cp_wtile(sb + SM_W1, g_wh + (size_t)(wlo + 2 * node + 1) * (KK * KK), tid);

    float4 p1r[4];
    float mx1r[4];
    #pragma unroll
    for (int it = 0; it < 4; it++) {
        const int r = it * 8 + wid;
        float4 p0, p1; float mx0, mx1;
        build_products(shin, node, b0, r, lane, p0, p1, mx0, mx1);
        float l0;
        store_A_row(As, r, lane, p0, pow2_inv(mx0, l0));
        p1r[it] = p1; mx1r[it] = mx1;
        if (lane == 0) {
            float l1t;
            pow2_inv(mx1, l1t);
            float Ma = minb[(size_t)(4 * node + 0) * BATCH + b0 + r];
            float Mb = minb[(size_t)(4 * node + 1) * BATCH + b0 + r];
            float Mc = minb[(size_t)(4 * node + 2) * BATCH + b0 + r];
            float Md = minb[(size_t)(4 * node + 3) * BATCH + b0 + r];
            Msum[r] = Ma + Mb + Mc + Md + l0 + l1t;
        }
    }

    AccFrag acc1[2], acc2[2];

    cp_wait<1>();
    __syncthreads();
    gemm32_acc(As, (const __half*)(smem + SM_W0), acc1, wid);
    __syncthreads();

    cp_wtile(sb + SM_W0, g_wh + (size_t)(wup + node) * (KK * KK), tid);

    #pragma unroll
    for (int it = 0; it < 4; it++) {
        float l1t;
        store_A_row(As, it * 8 + wid, lane, p1r[it], pow2_inv(mx1r[it], l1t));
    }

    cp_wait<1>();
    __syncthreads();
    gemm32_acc(As, (const __half*)(smem + SM_W1), acc2, wid);

    #pragma unroll
    for (int j = 0; j < 2; j++)
        #pragma unroll
        for (int e = 0; e < acc2[j].num_elements; e++)
            acc2[j].x[e] *= acc1[j].x[e];
    store_acc32(acc2, S0, wid);
    __syncthreads();

    #pragma unroll
    for (int it = 0; it < 4; it++) {
        const int r = it * 8 + wid;
        float4 p = *(const float4*)&S0[r * LDS + 4 * lane];
        float pmax = fmaxf(warp_max(max4(p)), 1e-35f);
        float la;
        store_A_row(As, r, lane, p, pow2_inv(pmax, la));
        if (lane == 0) Msum[r] += la;
    }

    cp_wait<0>();
    __syncthreads();
    gemm32_acc(As, (const __half*)(smem + SM_W0), acc2, wid);
    store_acc32(acc2, S0, wid);
    __syncthreads();

    if (FINAL) {
        const int r = tid >> 3, c0 = (tid & 7) * 16;
        const float mrow = Msum[r];
        float* orow = dout + ((size_t)node * BATCH + b0 + r) * KK + c0;
        #pragma unroll
        for (int c = 0; c < 4; c++) {
            float4 s = *(const float4*)&S0[r * LDS + c0 + 4 * c];
            float4 o;
            o.x = mrow + __logf(s.x); o.y = mrow + __logf(s.y);
            o.z = mrow + __logf(s.z); o.w = mrow + __logf(s.w);
            ((float4*)orow)[c] = o;
        }
    } else {
        const int r = tid >> 3, cg = tid & 7, c0 = cg * 16;
        float vmax = 0.0f;
        #pragma unroll
        for (int c = 0; c < 4; c++) {
            float4 s = *(const float4*)&S0[r * LDS + c0 + 4 * c];
            vmax = fmaxf(vmax, max4(s));
        }
        vmax = fmaxf(vmax, __shfl_xor_sync(0xffffffffu, vmax, 1));
        vmax = fmaxf(vmax, __shfl_xor_sync(0xffffffffu, vmax, 2));
        vmax = fmaxf(vmax, __shfl_xor_sync(0xffffffffu, vmax, 4));
        vmax = fmaxf(vmax, 1e-35f);
        float lv;
        const float inv = pow2_inv(vmax, lv);
        __half* orow = shout + ((size_t)node * BATCH + b0 + r) * KK + c0;
        #pragma unroll
        for (int q = 0; q < 2; q++) {
            float4 s0 = *(const float4*)&S0[r * LDS + c0 + 8 * q];
            float4 s1 = *(const float4*)&S0[r * LDS + c0 + 8 * q + 4];
            __half2 h0 = __floats2half2_rn(s0.x * inv, s0.y * inv);
            __half2 h1 = __floats2half2_rn(s0.z * inv, s0.w * inv);
            __half2 h2 = __floats2half2_rn(s1.x * inv, s1.y * inv);
            __half2 h3 = __floats2half2_rn(s1.z * inv, s1.w * inv);
            uint4 pk;
            pk.x = *(uint32_t*)&h0; pk.y = *(uint32_t*)&h1;
            pk.z = *(uint32_t*)&h2; pk.w = *(uint32_t*)&h3;
            *(uint4*)(orow + 8 * q) = pk;
        }
        if (cg == 0) mout[(size_t)node * BATCH + b0 + r] = Msum[r] + lv;
    }
}

extern "C" void kernel_launch(void* const* d_in, const int* in_sizes, int n_in,
                              void* d_out, int out_size) {
    const float* x  = (const float*)d_in[0];
    const float* mu = (const float*)d_in[1];
    const float* ls = (const float*)d_in[2];
    const float* w  = (const float*)d_in[3];
    float* out = (float*)d_out;

    cudaFuncSetAttribute(pair64_kernel<true>,  cudaFuncAttributeMaxDynamicSharedMemorySize, P64_BYTES);
    cudaFuncSetAttribute(pair64_kernel<false>, cudaFuncAttributeMaxDynamicSharedMemorySize, P64_BYTES);
    cudaFuncSetAttribute(pair32_kernel<false>, cudaFuncAttributeMaxDynamicSharedMemorySize, SMEM_BYTES);
    cudaFuncSetAttribute(pair32_kernel<true>,  cudaFuncAttributeMaxDynamicSharedMemorySize, SMEM_BYTES);

    softmax_w_kernel<<<1023, 256>>>(w);

    // pairs: (leaf512+256) (128+64) (32+16) (8+4) -> pair64; (2+1) -> pair32 FINAL
    pair64_kernel<true ><<<dim3(4, 256), 256, P64_BYTES>>>(-1, 0, 0,    512,  x, mu, ls); // -> sh0 (256)
    pair64_kernel<false><<<dim3(4, 64),  256, P64_BYTES>>>( 0, 1, 768,  896,  x, mu, ls); // -> sh1 (64)
    pair64_kernel<false><<<dim3(4, 16),  256, P64_BYTES>>>( 1, 0, 960,  992,  x, mu, ls); // -> sh0 (16)
    pair64_kernel<false><<<dim3(4, 4),   256, P64_BYTES>>>( 0, 1, 1008, 1016, x, mu, ls); // -> sh1 (4)
    pair32_kernel<true ><<<dim3(8, 1),   256, SMEM_BYTES>>>( 1, 2, 1020, 1022, out);      // -> out (root)
}

// round 17
// speedup vs baseline: 1.0973x; 1.0610x over previous
#include <cuda_runtime.h>
#include <cuda_fp16.h>
#include <mma.h>
#include <stdint.h>

using namespace nvcuda;

#define KK 128
#define BATCH 256
#define DD 1024
#define BK (BATCH*KK)
#define LDA 136           // halves per A/W smem row (272 B)
#define LDS 132           // floats per S smem row

// static scratch (allocation-free rule)
__device__ __half g_sh0[256 * BATCH * KK];
__device__ __half g_sh1[64 * BATCH * KK];
__device__ float  g_m0[256 * BATCH];
__device__ float  g_m1[64 * BATCH];
__device__ __half g_wh[1023 * KK * KK];      // softmax(W) fp16

// ---- pair32 smem layout ----
#define SM_W0   0
#define SM_W1   34816
#define SM_A    69632
#define SM_S0   78336
#define SM_MSUM 95232
#define SMEM_BYTES (SM_MSUM + 192)

// ---- pair64 smem layout (64 rows, 256 thr) ----
#define P64_W0   0
#define P64_W1   34816
#define P64_AR   34816      // alias of W1 (renormalized A after GEMM2)
#define P64_A0   69632
#define P64_A1   87040
#define P64_S0   69632      // alias A0+A1
#define P64_MSUM 104448
#define P64_PM   104704     // leaf params 10x128 f32
#define P64_BYTES (P64_PM + 5120 + 64)   // ~107.3 KB -> 2 blocks/SM

// ---------------- helpers ----------------
static __device__ __forceinline__ uint32_t smem_u32(const void* p) {
    uint32_t a;
    asm("{ .reg .u64 t; cvta.to.shared.u64 t, %1; cvt.u32.u64 %0, t; }" : "=r"(a) : "l"(p));
    return a;
}
static __device__ __forceinline__ void cp_async16(uint32_t dst, const void* src) {
    asm volatile("cp.async.cg.shared.global [%0], [%1], 16;" :: "r"(dst), "l"(src));
}
static __device__ __forceinline__ void cp_commit() {
    asm volatile("cp.async.commit_group;" ::: "memory");
}
template<int N> static __device__ __forceinline__ void cp_wait() {
    asm volatile("cp.async.wait_group %0;" :: "n"(N) : "memory");
}
static __device__ __forceinline__ float warp_max(float m) {
    #pragma unroll
    for (int o = 16; o; o >>= 1) m = fmaxf(m, __shfl_xor_sync(0xffffffffu, m, o));
    return m;
}
static __device__ __forceinline__ float max4(float4 v) {
    return fmaxf(fmaxf(v.x, v.y), fmaxf(v.z, v.w));
}
// power-of-two renorm: inv = 2^(127-E), logadd = (E-127)*ln2 (exact)
static __device__ __forceinline__ float pow2_inv(float pmax, float& logadd) {
    uint32_t E = __float_as_uint(pmax) >> 23;     // pmax clamped positive normal
    logadd = (float)((int)E - 127) * 0.6931471805599453f;
    return __uint_as_float((254u - E) << 23);
}

// ---------------- K0: softmax(W) -> fp16 ----------------
__global__ void __launch_bounds__(256) softmax_w_kernel(const float* __restrict__ w) {
    const int node = blockIdx.x;
    const int wid = threadIdx.x >> 5, lane = threadIdx.x & 31;
    const float* wn = w + (size_t)node * (KK * KK);
    __half* out = g_wh + (size_t)node * (KK * KK);
    #pragma unroll 4
    for (int i = wid; i < KK; i += 8) {
        float4 v = ((const float4*)(wn + i * KK))[lane];
        float m = warp_max(max4(v));
        float e0 = __expf(v.x - m), e1 = __expf(v.y - m);
        float e2 = __expf(v.z - m), e3 = __expf(v.w - m);
        float s = e0 + e1 + e2 + e3;
        #pragma unroll
        for (int o = 16; o; o >>= 1) s += __shfl_xor_sync(0xffffffffu, s, o);
        float inv = 1.0f / s;
        __half2 h0 = __floats2half2_rn(e0 * inv, e1 * inv);
        __half2 h1 = __floats2half2_rn(e2 * inv, e3 * inv);
        uint2 pk; pk.x = *(uint32_t*)&h0; pk.y = *(uint32_t*)&h1;
        *(uint2*)&out[i * KK + 4 * lane] = pk;
    }
}

using AccFrag = wmma::fragment<wmma::accumulator, 16, 16, 16, float>;

// 32x128x128: warp tile 16m x 32n
static __device__ __forceinline__ void gemm32_acc(const __half* As, const __half* Wh,
                                                  AccFrag acc[2], int wid) {
    const int m_base = (wid & 1) * 16, n_base = (wid >> 1) * 32;
    wmma::fill_fragment(acc[0], 0.0f);
    wmma::fill_fragment(acc[1], 0.0f);
    #pragma unroll
    for (int k = 0; k < 8; k++) {
        wmma::fragment<wmma::matrix_a, 16, 16, 16, __half, wmma::row_major> af;
        wmma::load_matrix_sync(af, &As[m_base * LDA + 16 * k], LDA);
        #pragma unroll
        for (int j = 0; j < 2; j++) {
            wmma::fragment<wmma::matrix_b, 16, 16, 16, __half, wmma::col_major> bf;
            wmma::load_matrix_sync(bf, &Wh[(n_base + 16 * j) * LDA + 16 * k], LDA);
            wmma::mma_sync(acc[j], af, bf, acc[j]);
        }
    }
}
static __device__ __forceinline__ void store_acc32(AccFrag acc[2], float* Out, int wid) {
    const int m_base = (wid & 1) * 16, n_base = (wid >> 1) * 32;
    #pragma unroll
    for (int j = 0; j < 2; j++)
        wmma::store_matrix_sync(&Out[m_base * LDS + n_base + 16 * j], acc[j], LDS,
                                wmma::mem_row_major);
}

// 64x128x128 (256 thr): warp grid 2m x 4n, warp tile 32m x 32n (acc[4])
static __device__ __forceinline__ void gemm64_acc(const __half* As, const __half* Wh,
                                                  AccFrag acc[4], int wid) {
    const int m_base = (wid & 1) * 32, n_base = (wid >> 1) * 32;
    #pragma unroll
    for (int i = 0; i < 4; i++) wmma::fill_fragment(acc[i], 0.0f);
    #pragma unroll
    for (int k = 0; k < 8; k++) {
        wmma::fragment<wmma::matrix_a, 16, 16, 16, __half, wmma::row_major> af[2];
        wmma::fragment<wmma::matrix_b, 16, 16, 16, __half, wmma::col_major> bf[2];
        #pragma unroll
        for (int i = 0; i < 2; i++)
            wmma::load_matrix_sync(af[i], &As[(m_base + 16 * i) * LDA + 16 * k], LDA);
        #pragma unroll
        for (int j = 0; j < 2; j++)
            wmma::load_matrix_sync(bf[j], &Wh[(n_base + 16 * j) * LDA + 16 * k], LDA);
        #pragma unroll
        for (int i = 0; i < 2; i++)
            #pragma unroll
            for (int j = 0; j < 2; j++)
                wmma::mma_sync(acc[2 * i + j], af[i], bf[j], acc[2 * i + j]);
    }
}
static __device__ __forceinline__ void store_acc64(AccFrag acc[4], float* Out, int wid) {
    const int m_base = (wid & 1) * 32, n_base = (wid >> 1) * 32;
    #pragma unroll
    for (int i = 0; i < 2; i++)
        #pragma unroll
        for (int j = 0; j < 2; j++)
            wmma::store_matrix_sync(&Out[(m_base + 16 * i) * LDS + n_base + 16 * j],
                                    acc[2 * i + j], LDS, wmma::mem_row_major);
}
static __device__ __forceinline__ void cp_wtile(uint32_t dst, const __half* wsrc, int tid) {
    const char* ws = (const char*)wsrc;
    #pragma unroll
    for (int c = tid; c < 2048; c += 256)
        cp_async16(dst + (c >> 4) * 272 + (c & 15) * 16, ws + (c >> 4) * 256 + (c & 15) * 16);
    cp_commit();
}
static __device__ __forceinline__ void store_A_row(
    __half* dst, int r, int lane, float4 p, float inv)
{
    __half2 h0 = __floats2half2_rn(p.x * inv, p.y * inv);
    __half2 h1 = __floats2half2_rn(p.z * inv, p.w * inv);
    uint2 pk; pk.x = *(uint32_t*)&h0; pk.y = *(uint32_t*)&h1;
    *(uint2*)&dst[r * LDA + 4 * lane] = pk;
}

// non-leaf build: load 4 children's normalized-S (fp16), products + rowmax
static __device__ __forceinline__ void build_products(
    const __half* shin, int node, int b0, int r, int lane,
    float4& p0, float4& p1, float& mx0, float& mx1)
{
    const __half* sp = shin + ((size_t)(4 * node) * BATCH + b0 + r) * KK;
    uint2 qa = ((const uint2*)sp)[lane];
    uint2 qb = ((const uint2*)(sp + BK))[lane];
    uint2 qc = ((const uint2*)(sp + 2 * BK))[lane];
    uint2 qd = ((const uint2*)(sp + 3 * BK))[lane];
    float2 a0 = __half22float2(*(__half2*)&qa.x), a1 = __half22float2(*(__half2*)&qa.y);
    float2 b0f = __half22float2(*(__half2*)&qb.x), b1f = __half22float2(*(__half2*)&qb.y);
    float2 c0 = __half22float2(*(__half2*)&qc.x), c1 = __half22float2(*(__half2*)&qc.y);
    float2 d0 = __half22float2(*(__half2*)&qd.x), d1 = __half22float2(*(__half2*)&qd.y);
    p0.x = a0.x * b0f.x; p0.y = a0.y * b0f.y; p0.z = a1.x * b1f.x; p0.w = a1.y * b1f.y;
    p1.x = c0.x * d0.x;  p1.y = c0.y * d0.y;  p1.z = c1.x * d1.x;  p1.w = c1.y * d1.y;
    mx0 = fmaxf(warp_max(max4(p0)), 1e-35f);
    mx1 = fmaxf(warp_max(max4(p1)), 1e-35f);
}

// ---------------- pair64: 64-row blocks, 256 threads (multi-wave levels) ----------------
template<bool LEAF>
__global__ void __launch_bounds__(256, 2) pair64_kernel(
    int insel, int outsel, int wlo, int wup,
    const float* __restrict__ x, const float* __restrict__ mu,
    const float* __restrict__ ls)
{
    extern __shared__ char smem[];
    __half* A0s = (__half*)(smem + P64_A0);
    __half* A1s = (__half*)(smem + P64_A1);
    __half* ARs = (__half*)(smem + P64_AR);
    float* S0  = (float*)(smem + P64_S0);
    float* Msum = (float*)(smem + P64_MSUM);
    float* Pm  = (float*)(smem + P64_PM);
    const uint32_t sb = smem_u32(smem);

    const int tid = threadIdx.x, wid = tid >> 5, lane = tid & 31;
    const int node = blockIdx.y;
    const int b0 = blockIdx.x * 64;

    const __half* shin = (insel == 0) ? g_sh0 : g_sh1;
    const float* minb  = (insel == 0) ? g_m0  : g_m1;
    __half* shout = (outsel == 0) ? g_sh0 : g_sh1;
    float* mout   = (outsel == 0) ? g_m0  : g_m1;

    cp_wtile(sb + P64_W0, g_wh + (size_t)(wlo + 2 * node) * (KK * KK), tid);
    cp_wtile(sb + P64_W1, g_wh + (size_t)(wlo + 2 * node + 1) * (KK * KK), tid);

    if (LEAF) {
        if (tid < 128) {
            int v0 = 4 * node, v1 = 4 * node + 1, v2 = 4 * node + 2, v3 = 4 * node + 3;
            float l0 = ls[v0 * KK + tid], l1 = ls[v1 * KK + tid];
            float l2 = ls[v2 * KK + tid], l3 = ls[v3 * KK + tid];
            Pm[0 * 128 + tid] = mu[v0 * KK + tid];
            Pm[1 * 128 + tid] = __expf(-l0);
            Pm[2 * 128 + tid] = mu[v1 * KK + tid];
            Pm[3 * 128 + tid] = __expf(-l1);
            Pm[4 * 128 + tid] = -l0 - l1 - 1.8378770664093453f;
            Pm[5 * 128 + tid] = mu[v2 * KK + tid];
            Pm[6 * 128 + tid] = __expf(-l2);
            Pm[7 * 128 + tid] = mu[v3 * KK + tid];
            Pm[8 * 128 + tid] = __expf(-l3);
            Pm[9 * 128 + tid] = -l2 - l3 - 1.8378770664093453f;
        }
        __syncthreads();
    }

    // ---- build BOTH A tiles (8 rows per warp) ----
    #pragma unroll
    for (int it = 0; it < 8; it++) {
        const int r = it * 8 + wid;
        if (LEAF) {
            float4 v0, v1;
            float4 xq = *(const float4*)&x[(size_t)(b0 + r) * DD + 4 * node];
            float4 ma0 = *(const float4*)&Pm[0 * 128 + 4 * lane];
            float4 ia0 = *(const float4*)&Pm[1 * 128 + 4 * lane];
            float4 mb0 = *(const float4*)&Pm[2 * 128 + 4 * lane];
            float4 ib0 = *(const float4*)&Pm[3 * 128 + 4 * lane];
            float4 cc0 = *(const float4*)&Pm[4 * 128 + 4 * lane];
            float4 ma1 = *(const float4*)&Pm[5 * 128 + 4 * lane];
            float4 ia1 = *(const float4*)&Pm[6 * 128 + 4 * lane];
            float4 mb1 = *(const float4*)&Pm[7 * 128 + 4 * lane];
            float4 ib1 = *(const float4*)&Pm[8 * 128 + 4 * lane];
            float4 cc1 = *(const float4*)&Pm[9 * 128 + 4 * lane];
            float t, u;
            t = (xq.x - ma0.x) * ia0.x; u = (xq.y - mb0.x) * ib0.x; v0.x = cc0.x - 0.5f * (t*t + u*u);
            t = (xq.x - ma0.y) * ia0.y; u = (xq.y - mb0.y) * ib0.y; v0.y = cc0.y - 0.5f * (t*t + u*u);
            t = (xq.x - ma0.z) * ia0.z; u = (xq.y - mb0.z) * ib0.z; v0.z = cc0.z - 0.5f * (t*t + u*u);
            t = (xq.x - ma0.w) * ia0.w; u = (xq.y - mb0.w) * ib0.w; v0.w = cc0.w - 0.5f * (t*t + u*u);
            t = (xq.z - ma1.x) * ia1.x; u = (xq.w - mb1.x) * ib1.x; v1.x = cc1.x - 0.5f * (t*t + u*u);
            t = (xq.z - ma1.y) * ia1.y; u = (xq.w - mb1.y) * ib1.y; v1.y = cc1.y - 0.5f * (t*t + u*u);
            t = (xq.z - ma1.z) * ia1.z; u = (xq.w - mb1.z) * ib1.z; v1.z = cc1.z - 0.5f * (t*t + u*u);
            t = (xq.z - ma1.w) * ia1.w; u = (xq.w - mb1.w) * ib1.w; v1.w = cc1.w - 0.5f * (t*t + u*u);
            float m0 = warp_max(max4(v0));
            float m1 = warp_max(max4(v1));
            float4 e0, e1;
            e0.x = __expf(v0.x - m0); e0.y = __expf(v0.y - m0);
            e0.z = __expf(v0.z - m0); e0.w = __expf(v0.w - m0);
            e1.x = __expf(v1.x - m1); e1.y = __expf(v1.y - m1);
            e1.z = __expf(v1.z - m1); e1.w = __expf(v1.w - m1);
            store_A_row(A0s, r, lane, e0, 1.0f);
            store_A_row(A1s, r, lane, e1, 1.0f);
            if (lane == 0) Msum[r] = m0 + m1;
        } else {
            float4 p0, p1; float mx0, mx1;
            build_products(shin, node, b0, r, lane, p0, p1, mx0, mx1);
            float l0, l1;
            float i0 = pow2_inv(mx0, l0);
            float i1 = pow2_inv(mx1, l1);
            store_A_row(A0s, r, lane, p0, i0);
            store_A_row(A1s, r, lane, p1, i1);
            if (lane == 0) {
                float Ma = minb[(size_t)(4 * node + 0) * BATCH + b0 + r];
                float Mb = minb[(size_t)(4 * node + 1) * BATCH + b0 + r];
                float Mc = minb[(size_t)(4 * node + 2) * BATCH + b0 + r];
                float Md = minb[(size_t)(4 * node + 3) * BATCH + b0 + r];
                Msum[r] = Ma + Mb + Mc + Md + l0 + l1;
            }
        }
    }

    AccFrag acc1[4], acc2[4];

    cp_wait<0>();            // W_c0 + W_c1 ready
    __syncthreads();

    gemm64_acc(A0s, (const __half*)(smem + P64_W0), acc1, wid);
    gemm64_acc(A1s, (const __half*)(smem + P64_W1), acc2, wid);

    #pragma unroll
    for (int i = 0; i < 4; i++)
        #pragma unroll
        for (int e = 0; e < acc2[i].num_elements; e++)
            acc2[i].x[e] *= acc1[i].x[e];

    __syncthreads();
    cp_wtile(sb + P64_W0, g_wh + (size_t)(wup + node) * (KK * KK), tid);   // W_up -> W0
    store_acc64(acc2, S0, wid);
    __syncthreads();

    // ---- renorm -> ARs (pow2 scale), Msum += k*ln2 ----
    #pragma unroll
    for (int it = 0; it < 8; it++) {
        const int r = it * 8 + wid;
        float4 p = *(const float4*)&S0[r * LDS + 4 * lane];
        float pmax = fmaxf(warp_max(max4(p)), 1e-35f);
        float la;
        float inv = pow2_inv(pmax, la);
        store_A_row(ARs, r, lane, p, inv);
        if (lane == 0) Msum[r] += la;
    }

    cp_wait<0>();            // W_up ready
    __syncthreads();
    gemm64_acc(ARs, (const __half*)(smem + P64_W0), acc1, wid);
    store_acc64(acc1, S0, wid);
    __syncthreads();

    // ---- epilogue: normalized fp16 S + M ----
    {
        const int r = tid >> 2, cg = tid & 3, c0 = cg * 32;
        float vmax = 0.0f;
        #pragma unroll
        for (int c = 0; c < 8; c++) {
            float4 s = *(const float4*)&S0[r * LDS + c0 + 4 * c];
            vmax = fmaxf(vmax, max4(s));
        }
        vmax = fmaxf(vmax, __shfl_xor_sync(0xffffffffu, vmax, 1));
        vmax = fmaxf(vmax, __shfl_xor_sync(0xffffffffu, vmax, 2));
        vmax = fmaxf(vmax, 1e-35f);
        float lv;
        const float inv = pow2_inv(vmax, lv);
        __half* orow = shout + ((size_t)node * BATCH + b0 + r) * KK + c0;
        #pragma unroll
        for (int q = 0; q < 4; q++) {
            float4 s0 = *(const float4*)&S0[r * LDS + c0 + 8 * q];
            float4 s1 = *(const float4*)&S0[r * LDS + c0 + 8 * q + 4];
            __half2 h0 = __floats2half2_rn(s0.x * inv, s0.y * inv);
            __half2 h1 = __floats2half2_rn(s0.z * inv, s0.w * inv);
            __half2 h2 = __floats2half2_rn(s1.x * inv, s1.y * inv);
            __half2 h3 = __floats2half2_rn(s1.z * inv, s1.w * inv);
            uint4 pk;
            pk.x = *(uint32_t*)&h0; pk.y = *(uint32_t*)&h1;
            pk.z = *(uint32_t*)&h2; pk.w = *(uint32_t*)&h3;
            *(uint4*)(orow + 8 * q) = pk;
        }
        if (cg == 0) mout[(size_t)node * BATCH + b0 + r] = Msum[r] + lv;
    }
}

// ---------------- pair32: 32-row blocks (1-wave levels; shortest chain) ----------------
template<bool FINAL>
__global__ void __launch_bounds__(256, 2) pair32_kernel(
    int insel, int outsel, int wlo, int wup, float* __restrict__ dout)
{
    extern __shared__ char smem[];
    __half* As = (__half*)(smem + SM_A);
    float* S0  = (float*)(smem + SM_S0);
    float* Msum = (float*)(smem + SM_MSUM);
    const uint32_t sb = smem_u32(smem);

    const int tid = threadIdx.x, wid = tid >> 5, lane = tid & 31;
    const int node = blockIdx.y;
    const int b0 = blockIdx.x * 32;

    const __half* shin = (insel == 0) ? g_sh0 : g_sh1;
    const float* minb  = (insel == 0) ? g_m0  : g_m1;
    __half* shout = (outsel == 0) ? g_sh0 : g_sh1;
    float* mout   = (outsel == 0) ? g_m0  : g_m1;

    cp_wtile(sb + SM_W0, g_wh + (size_t)(wlo + 2 * node) * (KK * KK), tid);
    cp_wtile(sb + SM_W1, g_wh + (size_t)(wlo + 2 * node + 1) * (KK * KK), tid);

    float4 p1r[4];
    float mx1r[4];
    #pragma unroll
    for (int it = 0; it < 4; it++) {
        const int r = it * 8 + wid;
        float4 p0, p1; float mx0, mx1;
        build_products(shin, node, b0, r, lane, p0, p1, mx0, mx1);
        float l0;
        store_A_row(As, r, lane, p0, pow2_inv(mx0, l0));
        p1r[it] = p1; mx1r[it] = mx1;
        if (lane == 0) {
            float l1t;
            pow2_inv(mx1, l1t);
            float Ma = minb[(size_t)(4 * node + 0) * BATCH + b0 + r];
            float Mb = minb[(size_t)(4 * node + 1) * BATCH + b0 + r];
            float Mc = minb[(size_t)(4 * node + 2) * BATCH + b0 + r];
            float Md = minb[(size_t)(4 * node + 3) * BATCH + b0 + r];
            Msum[r] = Ma + Mb + Mc + Md + l0 + l1t;
        }
    }

    AccFrag acc1[2], acc2[2];

    cp_wait<1>();
    __syncthreads();
    gemm32_acc(As, (const __half*)(smem + SM_W0), acc1, wid);
    __syncthreads();

    cp_wtile(sb + SM_W0, g_wh + (size_t)(wup + node) * (KK * KK), tid);

    #pragma unroll
    for (int it = 0; it < 4; it++) {
        float l1t;
        store_A_row(As, it * 8 + wid, lane, p1r[it], pow2_inv(mx1r[it], l1t));
    }

    cp_wait<1>();
    __syncthreads();
    gemm32_acc(As, (const __half*)(smem + SM_W1), acc2, wid);

    #pragma unroll
    for (int j = 0; j < 2; j++)
        #pragma unroll
        for (int e = 0; e < acc2[j].num_elements; e++)
            acc2[j].x[e] *= acc1[j].x[e];
    store_acc32(acc2, S0, wid);
    __syncthreads();

    #pragma unroll
    for (int it = 0; it < 4; it++) {
        const int r = it * 8 + wid;
        float4 p = *(const float4*)&S0[r * LDS + 4 * lane];
        float pmax = fmaxf(warp_max(max4(p)), 1e-35f);
        float la;
        store_A_row(As, r, lane, p, pow2_inv(pmax, la));
        if (lane == 0) Msum[r] += la;
    }

    cp_wait<0>();
    __syncthreads();
    gemm32_acc(As, (const __half*)(smem + SM_W0), acc2, wid);
    store_acc32(acc2, S0, wid);
    __syncthreads();

    if (FINAL) {
        const int r = tid >> 3, c0 = (tid & 7) * 16;
        const float mrow = Msum[r];
        float* orow = dout + ((size_t)node * BATCH + b0 + r) * KK + c0;
        #pragma unroll
        for (int c = 0; c < 4; c++) {
            float4 s = *(const float4*)&S0[r * LDS + c0 + 4 * c];
            float4 o;
            o.x = mrow + __logf(s.x); o.y = mrow + __logf(s.y);
            o.z = mrow + __logf(s.z); o.w = mrow + __logf(s.w);
            ((float4*)orow)[c] = o;
        }
    } else {
        const int r = tid >> 3, cg = tid & 7, c0 = cg * 16;
        float vmax = 0.0f;
        #pragma unroll
        for (int c = 0; c < 4; c++) {
            float4 s = *(const float4*)&S0[r * LDS + c0 + 4 * c];
            vmax = fmaxf(vmax, max4(s));
        }
        vmax = fmaxf(vmax, __shfl_xor_sync(0xffffffffu, vmax, 1));
        vmax = fmaxf(vmax, __shfl_xor_sync(0xffffffffu, vmax, 2));
        vmax = fmaxf(vmax, __shfl_xor_sync(0xffffffffu, vmax, 4));
        vmax = fmaxf(vmax, 1e-35f);
        float lv;
        const float inv = pow2_inv(vmax, lv);
        __half* orow = shout + ((size_t)node * BATCH + b0 + r) * KK + c0;
        #pragma unroll
        for (int q = 0; q < 2; q++) {
            float4 s0 = *(const float4*)&S0[r * LDS + c0 + 8 * q];
            float4 s1 = *(const float4*)&S0[r * LDS + c0 + 8 * q + 4];
            __half2 h0 = __floats2half2_rn(s0.x * inv, s0.y * inv);
            __half2 h1 = __floats2half2_rn(s0.z * inv, s0.w * inv);
            __half2 h2 = __floats2half2_rn(s1.x * inv, s1.y * inv);
            __half2 h3 = __floats2half2_rn(s1.z * inv, s1.w * inv);
            uint4 pk;
            pk.x = *(uint32_t*)&h0; pk.y = *(uint32_t*)&h1;
            pk.z = *(uint32_t*)&h2; pk.w = *(uint32_t*)&h3;
            *(uint4*)(orow + 8 * q) = pk;
        }
        if (cg == 0) mout[(size_t)node * BATCH + b0 + r] = Msum[r] + lv;
    }
}

extern "C" void kernel_launch(void* const* d_in, const int* in_sizes, int n_in,
                              void* d_out, int out_size) {
    const float* x  = (const float*)d_in[0];
    const float* mu = (const float*)d_in[1];
    const float* ls = (const float*)d_in[2];
    const float* w  = (const float*)d_in[3];
    float* out = (float*)d_out;

    cudaFuncSetAttribute(pair64_kernel<true>,  cudaFuncAttributeMaxDynamicSharedMemorySize, P64_BYTES);
    cudaFuncSetAttribute(pair64_kernel<false>, cudaFuncAttributeMaxDynamicSharedMemorySize, P64_BYTES);
    cudaFuncSetAttribute(pair32_kernel<false>, cudaFuncAttributeMaxDynamicSharedMemorySize, SMEM_BYTES);
    cudaFuncSetAttribute(pair32_kernel<true>,  cudaFuncAttributeMaxDynamicSharedMemorySize, SMEM_BYTES);

    softmax_w_kernel<<<1023, 256>>>(w);

    // multi-wave levels -> pair64; 1-wave levels -> pair32 (shortest chain)
    pair64_kernel<true ><<<dim3(4, 256), 256, P64_BYTES>>>(-1, 0, 0,    512,  x, mu, ls);  // -> sh0 (256)
    pair64_kernel<false><<<dim3(4, 64),  256, P64_BYTES>>>( 0, 1, 768,  896,  x, mu, ls);  // -> sh1 (64)
    pair32_kernel<false><<<dim3(8, 16),  256, SMEM_BYTES>>>( 1, 0, 960,  992,  out);       // -> sh0 (16)
    pair32_kernel<false><<<dim3(8, 4),   256, SMEM_BYTES>>>( 0, 1, 1008, 1016, out);       // -> sh1 (4)
    pair32_kernel<true ><<<dim3(8, 1),   256, SMEM_BYTES>>>( 1, 2, 1020, 1022, out);       // -> out (root)
}